// round 5
// baseline (speedup 1.0000x reference)
#include <cuda_runtime.h>
#include <cuda_fp16.h>

#define NN 100000
#define NE 1600000
#define NG 2048
#define HID 64
#define INF 14
#define EPSV 1e-5f
#define SCAN_B 1024
#define SCAN_NB ((NN + SCAN_B - 1) / SCAN_B)   // 98

// ---------------- scratch (device globals; no allocation allowed) -----------
__device__ __half2 g_Ah[NN * 32];     // 12.8 MB xw buffer (fp16)
__device__ float4  g_B[NN * 16];      // 25.6 MB h buffer (fp32)
__device__ float   g_dinv[NN];
__device__ float   g_stats[3][2 * HID];  // per-layer [sum(64), sumsq(64)]
__device__ int2    g_edge[NE];        // CSR-sorted (row, norm-bits)
__device__ int     g_cnt[NN];
__device__ int     g_off[NN + 1];
__device__ int     g_cur[NN];
__device__ int     g_bsum[SCAN_NB];
__device__ int     g_batch[NN];
__device__ int     g_is64;

// ---------------- index dtype detection -------------------------------------
__global__ void detect_k(const int* __restrict__ ei32) {
    __shared__ int any;
    if (threadIdx.x == 0) any = 0;
    __syncthreads();
    long i = 1 + 2L * threadIdx.x * 1562;
    if (i < 2L * NE && ei32[i] != 0) any = 1;
    __syncthreads();
    if (threadIdx.x == 0) g_is64 = (any == 0) ? 1 : 0;
}

__global__ void zero_nd_k() {
    int i = blockIdx.x * blockDim.x + threadIdx.x;
    if (i < NN) { g_cnt[i] = 0; g_dinv[i] = 0.f; }
    if (i < 3 * 2 * HID) ((float*)g_stats)[i] = 0.f;
}

// histogram (count + weighted degree) + batch conversion; no row/col staging
__global__ void convert_hist_k(const void* __restrict__ ei, const void* __restrict__ bt,
                               const float* __restrict__ w) {
    long t0 = (long)blockIdx.x * blockDim.x + threadIdx.x;
    long stride = (long)gridDim.x * blockDim.x;
    if (g_is64) {
        const long long* e = (const long long*)ei;
        const long long* b = (const long long*)bt;
        for (long i = t0; i < NE; i += stride) {
            int c = (int)e[NE + i];
            atomicAdd(&g_cnt[c], 1);
            atomicAdd(&g_dinv[c], w[i]);
        }
        for (long i = t0; i < NN; i += stride) g_batch[i] = (int)b[i];
    } else {
        const int* e = (const int*)ei;
        const int* b = (const int*)bt;
        for (long i = t0; i < NE; i += stride) {
            int c = e[NE + i];
            atomicAdd(&g_cnt[c], 1);
            atomicAdd(&g_dinv[c], w[i]);
        }
        for (long i = t0; i < NN; i += stride) g_batch[i] = b[i];
    }
}

// ---------------- scan pass 1 (block sums) + fused dinv ----------------------
__global__ void scan1_k() {
    __shared__ int sh[256];
    int base = blockIdx.x * SCAN_B;
    int s = 0;
    for (int i = threadIdx.x; i < SCAN_B; i += 256) {
        int idx = base + i;
        if (idx < NN) {
            s += g_cnt[idx];
            g_dinv[idx] = rsqrtf(g_dinv[idx] + 1.f);
        }
    }
    sh[threadIdx.x] = s;
    __syncthreads();
    for (int o = 128; o > 0; o >>= 1) {
        if (threadIdx.x < o) sh[threadIdx.x] += sh[threadIdx.x + o];
        __syncthreads();
    }
    if (threadIdx.x == 0) g_bsum[blockIdx.x] = sh[0];
}
__global__ void scan2_k() {
    __shared__ int sh[128];
    int t = threadIdx.x;
    int orig = (t < SCAN_NB) ? g_bsum[t] : 0;
    sh[t] = orig;
    __syncthreads();
    for (int o = 1; o < 128; o <<= 1) {
        int v = (t >= o) ? sh[t - o] : 0;
        __syncthreads();
        sh[t] += v;
        __syncthreads();
    }
    if (t < SCAN_NB) g_bsum[t] = sh[t] - orig;
    if (t == 127) g_off[NN] = sh[127];
}
__global__ void scan3_k() {
    __shared__ int sh[256];
    int base = blockIdx.x * SCAN_B;
    int i0 = base + threadIdx.x * 4;
    int vals[4];
    int tsum = 0;
#pragma unroll
    for (int k = 0; k < 4; k++) {
        int idx = i0 + k;
        vals[k] = (idx < NN) ? g_cnt[idx] : 0;
        tsum += vals[k];
    }
    sh[threadIdx.x] = tsum;
    __syncthreads();
    for (int o = 1; o < 256; o <<= 1) {
        int v = (threadIdx.x >= o) ? sh[threadIdx.x - o] : 0;
        __syncthreads();
        sh[threadIdx.x] += v;
        __syncthreads();
    }
    int excl = g_bsum[blockIdx.x] + sh[threadIdx.x] - tsum;
#pragma unroll
    for (int k = 0; k < 4; k++) {
        int idx = i0 + k;
        if (idx < NN) { g_off[idx] = excl; g_cur[idx] = excl; excl += vals[k]; }
    }
}

// scatter edges into CSR order as packed (row, norm)
__global__ void fill_k(const void* __restrict__ ei, const float* __restrict__ w) {
    long e = (long)blockIdx.x * 256 + threadIdx.x;
    if (e >= NE) return;
    int r, c;
    if (g_is64) {
        const long long* ee = (const long long*)ei;
        r = (int)ee[e]; c = (int)ee[NE + e];
    } else {
        const int* ee = (const int*)ei;
        r = ee[e]; c = ee[NE + e];
    }
    int pos = atomicAdd(&g_cur[c], 1);
    float nrm = g_dinv[r] * w[e] * g_dinv[c];
    g_edge[pos] = make_int2(r, __float_as_int(nrm));
}

// ---------------- dense xw = act(h) @ W -> fp16 out -------------------------
// BN coefs computed inline from stats buffer (no separate coef kernel).
template <int K, bool BN>
__global__ void xw_k(const float* __restrict__ x, const float* __restrict__ W,
                     __half2* __restrict__ outh, const float* __restrict__ stats,
                     const float* __restrict__ g, const float* __restrict__ bt) {
    __shared__ float Ws[K * HID];
    __shared__ float Xs[4][K];
    __shared__ float As[BN ? K : 1], Cs[BN ? K : 1];
    int tid = threadIdx.x;  // 256
    for (int i = tid; i < K * HID; i += 256) Ws[i] = W[i];
    if (BN && tid < K) {
        float mean = stats[tid] * (1.f / NN);
        float var = stats[64 + tid] * (1.f / NN) - mean * mean;
        float a = g[tid] * rsqrtf(var + EPSV);
        As[tid] = a;
        Cs[tid] = bt[tid] - mean * a;
    }
    __syncthreads();
    int node0 = blockIdx.x * 4;
    for (int i = tid; i < 4 * K; i += 256) {
        int nn = node0 + i / K;
        int f = i % K;
        float v = (nn < NN) ? x[(long)nn * K + f] : 0.f;
        if (BN) v = fmaxf(fmaf(As[f], v, Cs[f]), 0.f);
        Xs[i / K][f] = v;
    }
    __syncthreads();
    int node = node0 + tid / HID;
    int o = tid % HID;
    float acc = 0.f;
#pragma unroll
    for (int k = 0; k < K; k++) acc = fmaf(Xs[tid / HID][k], Ws[k * HID + o], acc);
    float hi = __shfl_down_sync(0xffffffffu, acc, 1);
    if (node < NN && (o & 1) == 0)
        outh[(long)node * 32 + (o >> 1)] = __floats2half2_rn(acc, hi);
}

// ---- CSR gather: warp per node, lane owns feats {2l, 2l+1}, unroll 4 -------
// grid = NN/16 = 6250, block = 512 (16 warps).
__global__ void gatherh_k(const __half2* __restrict__ xw, float2* __restrict__ out,
                          const float2* __restrict__ b2, float* __restrict__ stats) {
    __shared__ float sm[2 * HID];
    int tid = threadIdx.x;  // 512
    if (tid < 2 * HID) sm[tid] = 0.f;
    __syncthreads();

    int lane = tid & 31;
    int node = blockIdx.x * 16 + (tid >> 5);
    int start = g_off[node], end = g_off[node + 1];
    float d = g_dinv[node];
    float s = d * d;
    float2 bb = b2[lane];

    float2 sf = __half22float2(xw[(long)node * 32 + lane]);
    float ax = fmaf(s, sf.x, bb.x);
    float ay = fmaf(s, sf.y, bb.y);

    int j = start;
    for (; j + 3 < end; j += 4) {
        int2 e0 = g_edge[j], e1 = g_edge[j + 1], e2 = g_edge[j + 2], e3 = g_edge[j + 3];
        float2 v0 = __half22float2(xw[(long)e0.x * 32 + lane]);
        float2 v1 = __half22float2(xw[(long)e1.x * 32 + lane]);
        float2 v2 = __half22float2(xw[(long)e2.x * 32 + lane]);
        float2 v3 = __half22float2(xw[(long)e3.x * 32 + lane]);
        float n0 = __int_as_float(e0.y), n1 = __int_as_float(e1.y);
        float n2 = __int_as_float(e2.y), n3 = __int_as_float(e3.y);
        ax = fmaf(n0, v0.x, fmaf(n1, v1.x, fmaf(n2, v2.x, fmaf(n3, v3.x, ax))));
        ay = fmaf(n0, v0.y, fmaf(n1, v1.y, fmaf(n2, v2.y, fmaf(n3, v3.y, ay))));
    }
    for (; j < end; j++) {
        int2 e0 = g_edge[j];
        float2 v0 = __half22float2(xw[(long)e0.x * 32 + lane]);
        float n0 = __int_as_float(e0.y);
        ax = fmaf(n0, v0.x, ax);
        ay = fmaf(n0, v0.y, ay);
    }
    out[(long)node * 32 + lane] = make_float2(ax, ay);

    // fused BN stats: each lane owns distinct feats; reduce across the 16
    // warps of the block in smem, one global flush per block.
    atomicAdd(&sm[2 * lane], ax);
    atomicAdd(&sm[2 * lane + 1], ay);
    atomicAdd(&sm[64 + 2 * lane], ax * ax);
    atomicAdd(&sm[64 + 2 * lane + 1], ay * ay);
    __syncthreads();
    if (tid < 2 * HID) atomicAdd(&stats[tid], sm[tid]);
}

// ---------------- final: bn+relu apply, write node_out, pool to gemb --------
__global__ void zero4_k(float4* __restrict__ p, long n) {
    long t = (long)blockIdx.x * blockDim.x + threadIdx.x;
    if (t < n) p[t] = make_float4(0.f, 0.f, 0.f, 0.f);
}
__global__ void bnrelu_seg_k(const float4* __restrict__ h, float4* __restrict__ no,
                             float4* __restrict__ ge, const float* __restrict__ stats,
                             const float* __restrict__ g, const float* __restrict__ bt) {
    __shared__ float As[HID], Cs[HID];
    int tid = threadIdx.x;
    if (tid < HID) {
        float mean = stats[tid] * (1.f / NN);
        float var = stats[64 + tid] * (1.f / NN) - mean * mean;
        float a = g[tid] * rsqrtf(var + EPSV);
        As[tid] = a;
        Cs[tid] = bt[tid] - mean * a;
    }
    __syncthreads();
    long t = (long)blockIdx.x * 256 + tid;
    if (t >= (long)NN * 16) return;
    int node = (int)(t >> 4);
    int q = (int)(t & 15);
    int f0 = q * 4;
    float4 v = h[t];
    float r[4] = {v.x, v.y, v.z, v.w};
#pragma unroll
    for (int jj = 0; jj < 4; jj++)
        r[jj] = fmaxf(fmaf(As[f0 + jj], r[jj], Cs[f0 + jj]), 0.f);
    float4 res = make_float4(r[0], r[1], r[2], r[3]);
    no[t] = res;
    atomicAdd(&ge[(long)g_batch[node] * 16 + q], res);
}

__global__ void fc_k(const float* __restrict__ ge, const float* __restrict__ W,
                     const float* __restrict__ b, float* __restrict__ out) {
    int t = blockIdx.x * blockDim.x + threadIdx.x;
    if (t >= NG * 2) return;
    int g = t >> 1, c = t & 1;
    float acc = b[c];
#pragma unroll
    for (int f = 0; f < 64; f++) acc = fmaf(ge[g * 64 + f], W[f * 2 + c], acc);
    out[t] = acc;
}

// ---------------- orchestration ----------------------------------------------
extern "C" void kernel_launch(void* const* d_in, const int* in_sizes, int n_in,
                              void* d_out, int out_size) {
    const float* x  = (const float*)d_in[0];
    const void*  ei = d_in[1];
    const void*  bt = d_in[2];
    const float* ew = (const float*)d_in[3];
    const float* W1 = (const float*)d_in[4];
    const float* b1 = (const float*)d_in[5];
    const float* W2 = (const float*)d_in[6];
    const float* b2 = (const float*)d_in[7];
    const float* W3 = (const float*)d_in[8];
    const float* b3 = (const float*)d_in[9];
    const float* g1 = (const float*)d_in[10];
    const float* t1 = (const float*)d_in[11];
    const float* g2 = (const float*)d_in[12];
    const float* t2 = (const float*)d_in[13];
    const float* g3 = (const float*)d_in[14];
    const float* t3 = (const float*)d_in[15];
    const float* fcW = (const float*)d_in[16];
    const float* fcb = (const float*)d_in[17];

    float* out      = (float*)d_out;
    float* node_out = out + NG * 2;
    float* gemb     = node_out + (long)NN * HID;

    __half2* A;
    float4* B;
    float* S;
    cudaGetSymbolAddress((void**)&A, g_Ah);
    cudaGetSymbolAddress((void**)&B, g_B);
    cudaGetSymbolAddress((void**)&S, g_stats);
    float4* NO = (float4*)node_out;

    const int NB_N   = (NN + 255) / 256;                    // 391
    const int NB_E   = (NE + 255) / 256;                    // 6250
    const int NB_NF4 = (int)(((long)NN * 16 + 255) / 256);  // 6250
    const int NB_G   = NN / 16;                             // 6250 (512-thread blocks)

    // ---- CSR build (once, reused by all 3 layers)
    detect_k<<<1, 1024>>>((const int*)ei);
    zero_nd_k<<<NB_N, 256>>>();
    convert_hist_k<<<2048, 256>>>(ei, bt, ew);
    scan1_k<<<SCAN_NB, 256>>>();
    scan2_k<<<1, 128>>>();
    scan3_k<<<SCAN_NB, 256>>>();
    fill_k<<<NB_E, 256>>>(ei, ew);

    // ---- layer 1
    xw_k<INF, false><<<NN / 4, 256>>>(x, W1, A, nullptr, nullptr, nullptr);
    gatherh_k<<<NB_G, 512>>>(A, (float2*)B, (const float2*)b1, S);

    // ---- layer 2 (BN+ReLU of layer 1 folded into xw input)
    xw_k<HID, true><<<NN / 4, 256>>>((const float*)B, W2, A, S, g1, t1);
    gatherh_k<<<NB_G, 512>>>(A, (float2*)B, (const float2*)b2, S + 128);

    // ---- layer 3
    xw_k<HID, true><<<NN / 4, 256>>>((const float*)B, W3, A, S + 128, g2, t2);
    gatherh_k<<<NB_G, 512>>>(A, (float2*)B, (const float2*)b3, S + 256);

    // ---- fused bn+relu apply + pooling, then fc
    zero4_k<<<(NG * 16 + 255) / 256, 256>>>((float4*)gemb, (long)NG * 16);
    bnrelu_seg_k<<<NB_NF4, 256>>>(B, NO, (float4*)gemb, S + 256, g3, t3);
    fc_k<<<(NG * 2 + 255) / 256, 256>>>(gemb, fcW, fcb, out);
}